// round 13
// baseline (speedup 1.0000x reference)
#include <cuda_runtime.h>
#include <cuda_bf16.h>
#include <math.h>

typedef unsigned long long u64;
typedef unsigned int u32;

#define NEL  16
#define NPV  32
#define PSTR 33
#define BW   2048
#define MR   (BW * NEL)
#define ASTR 24   // smem row stride in bf16 (48B: 16B-aligned, conflict-staggered)

__device__ __align__(16) __nv_bfloat16 g_xc[2][(size_t)MR * 960];   // compact [h|m|l] x 320
__device__ __align__(16) float         g_s0[(size_t)MR * 256];
__device__ __align__(16) float         g_s1[(size_t)MR * 256];
__device__ __align__(16) float         g_pud[5][(size_t)BW * 1024];
__device__ __align__(16) float         g_base[BW * 256];
__device__ __align__(16) float         g_env[MR];
__device__ __align__(16) float         g_sw[(size_t)MR * 128];
__device__ __align__(16) __nv_bfloat16 g_mcat[(size_t)BW * 1536];   // compact [h|m|l] x 512
__device__ __align__(16) __nv_bfloat16 g_wscat[5][256 * 1920];      // 6 slots x 320
__device__ __align__(16) __nv_bfloat16 g_wmcat[5][256 * 3072];      // 6 slots x 512
__device__ __align__(16) __nv_bfloat16 g_worb[256 * 1536];          // 6 slots x 256
__device__ __align__(16) float         g_obias[256];
__device__ __align__(16) float         g_sbias[5][256];

__device__ __forceinline__ float fast_tanh(float x) {
    float e, r;
    asm("ex2.approx.f32 %0, %1;" : "=f"(e) : "f"(x * 2.885390082f));
    asm("rcp.approx.f32 %0, %1;" : "=f"(r) : "f"(e + 1.0f));
    return fmaf(-2.0f, r, 1.0f);
}
__device__ __forceinline__ u32 smem_u32(const void* p) {
    u32 a;
    asm("{ .reg .u64 t; cvta.to.shared.u64 t, %1; cvt.u32.u64 %0, t; }" : "=r"(a) : "l"(p));
    return a;
}
// three-way bf16 split: x ~= h + m + l to ~27 bits
__device__ __forceinline__ void split3(float x, __nv_bfloat16& h, __nv_bfloat16& m,
                                       __nv_bfloat16& l) {
    h = __float2bfloat16(x);
    float r1 = x - __bfloat162float(h);
    m = __float2bfloat16(r1);
    float r2 = r1 - __bfloat162float(m);
    l = __float2bfloat16(r2);
}
__device__ __forceinline__ u32 pk(__nv_bfloat16 a, __nv_bfloat16 b) {
    return ((u32)__bfloat16_as_ushort(b) << 16) | (u32)__bfloat16_as_ushort(a);
}
__device__ __forceinline__ void ldmat4(u32* r, u32 addr) {
    asm volatile("ldmatrix.sync.aligned.m8n8.x4.shared.b16 {%0,%1,%2,%3}, [%4];"
                 : "=r"(r[0]), "=r"(r[1]), "=r"(r[2]), "=r"(r[3]) : "r"(addr));
}
__device__ __forceinline__ void mma16816(float* d, const u32* a, const u32* b) {
    asm volatile(
        "mma.sync.aligned.m16n8k16.row.col.f32.bf16.bf16.f32 "
        "{%0,%1,%2,%3}, {%4,%5,%6,%7}, {%8,%9}, {%0,%1,%2,%3};"
        : "+f"(d[0]), "+f"(d[1]), "+f"(d[2]), "+f"(d[3])
        : "r"(a[0]), "r"(a[1]), "r"(a[2]), "r"(a[3]), "r"(b[0]), "r"(b[1]));
}
__device__ __forceinline__ float* sbuf(int p) { return p ? g_s1 : g_s0; }

// slot j computes A[amap[j]] * W[wver[j]]:
//   products: h*h, m*h, h*m, l*h, m*m, h*l  (missing terms all <= 2^-27)
__device__ __constant__ int c_amap[6] = {0, 1, 0, 2, 1, 0};

// ---------------- weight prep ----------------
__global__ void prepK(const float* __restrict__ sW, const float* __restrict__ vW,
                      const float* __restrict__ wuW, const float* __restrict__ wdW,
                      const float* __restrict__ sb, const float* __restrict__ vb,
                      const float* __restrict__ wub, const float* __restrict__ wdb) {
    int gt = blockIdx.x * blockDim.x + threadIdx.x, gs = gridDim.x * blockDim.x;
    // wver[6] = {h,h,m,h,m,l} encoded 0,0,1,0,1,2
    for (int i = gt; i < 5 * 256 * 1920; i += gs) {
        int L = i / (256 * 1920), r2 = i % (256 * 1920), n = r2 / 1920, k = r2 % 1920;
        const float* W = (L < 4) ? sW + (size_t)L * 832 * 256 : vW;
        int slot = k / 320, km = k % 320;
        int kr = (km < 256) ? km : 512 + km;
        float v = W[(size_t)kr * 256 + n];
        __nv_bfloat16 h, m, l; split3(v, h, m, l);
        int ver = (slot == 2 || slot == 4) ? 1 : (slot == 5 ? 2 : 0);
        g_wscat[L][n * 1920 + k] = (ver == 0) ? h : (ver == 1 ? m : l);
    }
    for (int i = gt; i < 5 * 256 * 3072; i += gs) {
        int L = i / (256 * 3072), r2 = i % (256 * 3072), n = r2 / 3072, k = r2 % 3072;
        const float* W = (L < 4) ? sW + (size_t)L * 832 * 256 : vW;
        int slot = k / 512;
        int kr = 256 + (k % 512);
        float v = W[(size_t)kr * 256 + n];
        __nv_bfloat16 h, m, l; split3(v, h, m, l);
        int ver = (slot == 2 || slot == 4) ? 1 : (slot == 5 ? 2 : 0);
        g_wmcat[L][n * 3072 + k] = (ver == 0) ? h : (ver == 1 ? m : l);
    }
    for (int i = gt; i < 256 * 1536; i += gs) {
        int n = i / 1536, k = i % 1536;
        int slot = k / 256, kk = k % 256;
        float v = (n < 128) ? wuW[kk * 128 + n] : wdW[kk * 128 + (n - 128)];
        __nv_bfloat16 h, m, l; split3(v, h, m, l);
        int ver = (slot == 2 || slot == 4) ? 1 : (slot == 5 ? 2 : 0);
        g_worb[n * 1536 + k] = (ver == 0) ? h : (ver == 1 ? m : l);
    }
    for (int i = gt; i < 256; i += gs) g_obias[i] = (i < 128) ? wub[i] : wdb[i - 128];
    for (int i = gt; i < 5 * 256; i += gs) {
        int L = i >> 8, c = i & 255;
        g_sbias[L][c] = (L < 4) ? sb[L * 256 + c] : vb[c];
    }
}

// ---------------- Phase A: embedding + layer-0 s + full p-stream ----------------
template <int KIN, bool RES>
__device__ void pA_mm(float* p, const float* __restrict__ W, const float* __restrict__ bias,
                      float* pw, float* pbv, int tid) {
    for (int i = tid; i < KIN * NPV; i += 256) pw[i] = __ldg(W + i);
    if (tid < NPV) pbv[tid] = __ldg(bias + tid);
    __syncthreads();
    float* prow = p + tid * PSTR;
    float pin[KIN];
#pragma unroll
    for (int k = 0; k < KIN; ++k) pin[k] = prow[k];
#pragma unroll
    for (int cb = 0; cb < NPV; cb += 4) {
        float4 a = *(const float4*)(pbv + cb);
#pragma unroll
        for (int k = 0; k < KIN; ++k) {
            float4 w = *(const float4*)(pw + k * NPV + cb);
            a.x = fmaf(pin[k], w.x, a.x); a.y = fmaf(pin[k], w.y, a.y);
            a.z = fmaf(pin[k], w.z, a.z); a.w = fmaf(pin[k], w.w, a.w);
        }
        prow[cb + 0] = RES ? fast_tanh(a.x) + pin[cb + 0] : fast_tanh(a.x);
        prow[cb + 1] = RES ? fast_tanh(a.y) + pin[cb + 1] : fast_tanh(a.y);
        prow[cb + 2] = RES ? fast_tanh(a.z) + pin[cb + 2] : fast_tanh(a.z);
        prow[cb + 3] = RES ? fast_tanh(a.w) + pin[cb + 3] : fast_tanh(a.w);
    }
    __syncthreads();
}

__device__ void pA_means(float* dst, const float* p, int tid) {
    for (int idx = tid; idx < 512; idx += 256) {
        int j = idx >> 5, f = idx & 31;
        float a = 0.f, b = 0.f;
#pragma unroll
        for (int i = 0; i < 8; ++i) a += p[(i * NEL + j) * PSTR + f];
#pragma unroll
        for (int i = 8; i < NEL; ++i) b += p[(i * NEL + j) * PSTR + f];
        dst[j * 32 + f] = a * 0.125f;
        dst[512 + j * 32 + f] = b * 0.125f;
    }
    __syncthreads();
}

__global__ void __launch_bounds__(256) phaseAK(
    const float* __restrict__ r, const float* __restrict__ a,
    const float* __restrict__ sW0, const float* __restrict__ sb0,
    const float* __restrict__ pW0, const float* __restrict__ pb0,
    const float* __restrict__ pW, const float* __restrict__ pb) {
    __shared__ float p[256 * PSTR];
    __shared__ float x[256], mu0[16], md0[16], pu0[64], pd0[64];
    __shared__ float pw[1024], pbv[32], r_s[48], a_s[12];
    const int tid = threadIdx.x, b = blockIdx.x;

    if (tid < 48) r_s[tid] = r[b * 48 + tid];
    if (tid >= 64 && tid < 76) a_s[tid - 64] = a[tid - 64];
    __syncthreads();

    if (tid < 16) {
        int e = tid;
        float rx = r_s[e * 3], ry = r_s[e * 3 + 1], rz = r_s[e * 3 + 2];
        float envv = 0.f;
#pragma unroll
        for (int at = 0; at < 4; ++at) {
            float dx = rx - a_s[at * 3], dy = ry - a_s[at * 3 + 1], dz = rz - a_s[at * 3 + 2];
            float l = sqrtf(dx * dx + dy * dy + dz * dz);
            x[e * 16 + at * 4 + 0] = dx; x[e * 16 + at * 4 + 1] = dy;
            x[e * 16 + at * 4 + 2] = dz; x[e * 16 + at * 4 + 3] = l;
            envv += expf(-l);
        }
        g_env[b * 16 + e] = envv;
    }
    {
        int i = tid >> 4, j = tid & 15;
        float dx = r_s[j * 3] - r_s[i * 3];
        float dy = r_s[j * 3 + 1] - r_s[i * 3 + 1];
        float dz = r_s[j * 3 + 2] - r_s[i * 3 + 2];
        float l = (i == j) ? sqrtf(3.0f) : sqrtf(dx * dx + dy * dy + dz * dz);
        float* prow = p + tid * PSTR;
        prow[0] = dx; prow[1] = dy; prow[2] = dz; prow[3] = l;
    }
    __syncthreads();
    if (tid < 16) {
        float mu = 0.f, md = 0.f;
#pragma unroll
        for (int e = 0; e < 8; ++e) mu += x[e * 16 + tid];
#pragma unroll
        for (int e = 8; e < 16; ++e) md += x[e * 16 + tid];
        mu0[tid] = mu * 0.125f; md0[tid] = md * 0.125f;
    }
    if (tid < 128) {
        int half = tid >> 6, t2 = tid & 63, j = t2 >> 2, f = t2 & 3;
        float s = 0.f;
        if (half == 0) {
#pragma unroll
            for (int i = 0; i < 8; ++i) s += p[(i * NEL + j) * PSTR + f];
            pu0[j * 4 + f] = s * 0.125f;
        } else {
#pragma unroll
            for (int i = 8; i < 16; ++i) s += p[(i * NEL + j) * PSTR + f];
            pd0[j * 4 + f] = s * 0.125f;
        }
    }
    __syncthreads();

    // layer-0 s (K=56): thread = output column; writes s0, xc[0] (h|m|l), mcat
    {
        int c = tid;
        float acc[16];
#pragma unroll
        for (int e = 0; e < 16; ++e) acc[e] = 0.f;
        float bse = __ldg(sb0 + c);
#pragma unroll
        for (int k = 0; k < 16; ++k) {
            float w = __ldg(sW0 + k * 256 + c);
#pragma unroll
            for (int e = 0; e < 16; ++e) acc[e] = fmaf(x[e * 16 + k], w, acc[e]);
            bse = fmaf(mu0[k], __ldg(sW0 + (16 + k) * 256 + c), bse);
            bse = fmaf(md0[k], __ldg(sW0 + (32 + k) * 256 + c), bse);
        }
#pragma unroll
        for (int f = 0; f < 4; ++f) {
            float wpu = __ldg(sW0 + (48 + f) * 256 + c);
            float wpd = __ldg(sW0 + (52 + f) * 256 + c);
#pragma unroll
            for (int e = 0; e < 16; ++e)
                acc[e] = fmaf(pu0[e * 4 + f], wpu, fmaf(pd0[e * 4 + f], wpd, acc[e]));
        }
        float mu = 0.f, md = 0.f;
        __nv_bfloat16 h, m, l;
#pragma unroll
        for (int e = 0; e < 16; ++e) {
            float sv = fast_tanh(acc[e] + bse);
            if (e < 8) mu += sv; else md += sv;
            g_s0[(size_t)(b * 16 + e) * 256 + c] = sv;
            split3(sv, h, m, l);
            __nv_bfloat16* xr = g_xc[0] + (size_t)(b * 16 + e) * 960;
            xr[c] = h; xr[320 + c] = m; xr[640 + c] = l;
        }
        __nv_bfloat16* mr = g_mcat + (size_t)b * 1536;
        split3(mu * 0.125f, h, m, l); mr[c] = h; mr[512 + c] = m; mr[1024 + c] = l;
        split3(md * 0.125f, h, m, l); mr[256 + c] = h; mr[768 + c] = m; mr[1280 + c] = l;
    }

    pA_mm<4, false>(p, pW0, pb0, pw, pbv, tid);
    pA_means(&g_pud[0][(size_t)b * 1024], p, tid);
#pragma unroll 1
    for (int i = 0; i < 4; ++i) {
        pA_mm<32, true>(p, pW + i * 1024, pb + i * 32, pw, pbv, tid);
        pA_means(&g_pud[i + 1][(size_t)b * 1024], p, tid);
    }
}

__global__ void pudfillK(int L) {
    int i = blockIdx.x * blockDim.x + threadIdx.x;
    int b = i >> 9, t = i & 511, e = t >> 5, f = t & 31;
    float vu = g_pud[L][(size_t)b * 1024 + e * 32 + f];
    float vd = g_pud[L][(size_t)b * 1024 + 512 + e * 32 + f];
    __nv_bfloat16 hu, mu, lu, hd, md, ld;
    split3(vu, hu, mu, lu); split3(vd, hd, md, ld);
    __nv_bfloat16* xr = g_xc[L & 1] + (size_t)(b * 16 + e) * 960;
    xr[256 + f] = hu; xr[288 + f] = hd;
    xr[576 + f] = mu; xr[608 + f] = md;
    xr[896 + f] = lu; xr[928 + f] = ld;
}

__global__ void meansK(int par) {
    int b = blockIdx.x, c = threadIdx.x;
    const float* s = sbuf(par) + (size_t)b * 16 * 256;
    float mu = 0.f, md = 0.f;
#pragma unroll
    for (int e = 0; e < 8; ++e) mu += s[e * 256 + c];
#pragma unroll
    for (int e = 8; e < 16; ++e) md += s[e * 256 + c];
    __nv_bfloat16 h, m, l;
    __nv_bfloat16* mr = g_mcat + (size_t)b * 1536;
    split3(mu * 0.125f, h, m, l); mr[c] = h; mr[512 + c] = m; mr[1024 + c] = l;
    split3(md * 0.125f, h, m, l); mr[256 + c] = h; mr[768 + c] = m; mr[1280 + c] = l;
}

// ---------------- mma.sync GEMM: CTA 128x128, warp 32x64, double-buffered ----------------
// A is COMPACT [h|m|l]; per k-step the A-block is picked via c_amap (6 slots).
// MODE 0: base   M=2048  K=6x512   A=g_mcat(1536)   B=g_wmcat(3072)
// MODE 1: s-res  M=32768 K=6x320   A=g_xc  (960)    B=g_wscat(1920)
// MODE 2: final  (as 1, no residual)
// MODE 3: orbit  M=32768 K=6x256   A=g_xc s-part    B=g_worb (1536)
template <int MODE>
__global__ void __launch_bounds__(256, 2) gemmK(int L) {
    __shared__ __nv_bfloat16 As[2][128 * ASTR];
    __shared__ __nv_bfloat16 Bs[2][128 * ASTR];
    const int tid = threadIdx.x, lane = tid & 31, warp = tid >> 5;
    const int wm = warp & 3, wn = warp >> 2;
    const int gid = lane >> 2, tig = lane & 3;

    const __nv_bfloat16 *A, *B;
    int lda, ldb, NS;
    if (MODE == 0)      { A = g_mcat;      B = g_wmcat[L]; lda = 1536; ldb = 3072; NS = 192; }
    else if (MODE == 3) { A = g_xc[1];     B = g_worb;     lda = 960;  ldb = 1536; NS = 96;  }
    else                { A = g_xc[L & 1]; B = g_wscat[L]; lda = 960;  ldb = 1920; NS = 120; }
    const int m0 = blockIdx.x * 128, n0 = blockIdx.y * 128;
    const int lr = tid >> 1, lh = (tid & 1) * 8;

    float acc[2][8][4];
#pragma unroll
    for (int i = 0; i < 2; ++i)
#pragma unroll
        for (int j = 0; j < 8; ++j)
#pragma unroll
            for (int k = 0; k < 4; ++k) acc[i][j][k] = 0.f;

    // A-block offset for k-step t
    auto aoff = [&](int t) -> int {
        int slot, within, blk;
        if (MODE == 0)      { slot = t >> 5; within = t & 31; blk = 512; }
        else if (MODE == 3) { slot = t >> 4; within = t & 15; blk = 320; }
        else                { slot = t / 20; within = t - slot * 20; blk = 320; }
        return c_amap[slot] * blk + within * 16;
    };

    // preload k-step 0
    {
        uint4 av = __ldg((const uint4*)(A + (size_t)(m0 + lr) * lda + aoff(0) + lh));
        uint4 bv = __ldg((const uint4*)(B + (size_t)(n0 + lr) * ldb + lh));
        *(uint4*)(&As[0][lr * ASTR + lh]) = av;
        *(uint4*)(&Bs[0][lr * ASTR + lh]) = bv;
    }
    __syncthreads();

    uint4 apre, bpre;
#pragma unroll 1
    for (int s = 0; s < NS; ++s) {
        const int buf = s & 1;
        if (s + 1 < NS) {
            apre = __ldg((const uint4*)(A + (size_t)(m0 + lr) * lda + aoff(s + 1) + lh));
            bpre = __ldg((const uint4*)(B + (size_t)(n0 + lr) * ldb + (s + 1) * 16 + lh));
        }
        u32 abase = smem_u32(&As[buf][0]);
        u32 bbase = smem_u32(&Bs[buf][0]);
        u32 af[2][4], bq[4][4];
        ldmat4(af[0], abase + ((wm * 32 + (lane & 15)) * ASTR + (lane >> 4) * 8) * 2);
        ldmat4(af[1], abase + ((wm * 32 + 16 + (lane & 15)) * ASTR + (lane >> 4) * 8) * 2);
#pragma unroll
        for (int q = 0; q < 4; ++q)
            ldmat4(bq[q], bbase + ((wn * 64 + q * 16 + (lane & 7) + ((lane >> 4) << 3)) * ASTR
                                   + ((lane >> 3) & 1) * 8) * 2);
#pragma unroll
        for (int mt = 0; mt < 2; ++mt)
#pragma unroll
            for (int nt = 0; nt < 8; ++nt)
                mma16816(acc[mt][nt], af[mt], &bq[nt >> 1][(nt & 1) * 2]);
        if (s + 1 < NS) {
            *(uint4*)(&As[buf ^ 1][lr * ASTR + lh]) = apre;
            *(uint4*)(&Bs[buf ^ 1][lr * ASTR + lh]) = bpre;
        }
        __syncthreads();
    }

    // epilogue
    const int rb = m0 + wm * 32, cb0 = n0 + wn * 64;
#pragma unroll
    for (int mt = 0; mt < 2; ++mt) {
        const int r0 = rb + mt * 16 + gid, r1 = r0 + 8;
#pragma unroll
        for (int nt = 0; nt < 8; ++nt) {
            const int c = cb0 + nt * 8 + tig * 2;
            float* d = acc[mt][nt];
            if (MODE == 0) {
                float b0v = g_sbias[L][c], b1v = g_sbias[L][c + 1];
                *(float2*)&g_base[(size_t)r0 * 256 + c] = make_float2(d[0] + b0v, d[1] + b1v);
                *(float2*)&g_base[(size_t)r1 * 256 + c] = make_float2(d[2] + b0v, d[3] + b1v);
            } else if (MODE == 1 || MODE == 2) {
                const float* bas = g_base + (size_t)(r0 >> 4) * 256;
                float v00 = fast_tanh(d[0] + bas[c]);
                float v01 = fast_tanh(d[1] + bas[c + 1]);
                float v10 = fast_tanh(d[2] + bas[c]);
                float v11 = fast_tanh(d[3] + bas[c + 1]);
                if (MODE == 1) {
                    const float* rs = sbuf(L & 1);
                    float* so = sbuf((L & 1) ^ 1);
                    float2 q0 = *(const float2*)&rs[(size_t)r0 * 256 + c];
                    float2 q1 = *(const float2*)&rs[(size_t)r1 * 256 + c];
                    v00 += q0.x; v01 += q0.y; v10 += q1.x; v11 += q1.y;
                    *(float2*)&so[(size_t)r0 * 256 + c] = make_float2(v00, v01);
                    *(float2*)&so[(size_t)r1 * 256 + c] = make_float2(v10, v11);
                }
                __nv_bfloat16 h0, m0b, l0, h1, m1b, l1;
                char* x0 = (char*)(g_xc[(L & 1) ^ 1] + (size_t)r0 * 960);
                split3(v00, h0, m0b, l0); split3(v01, h1, m1b, l1);
                *(u32*)(x0 + 2 * c) = pk(h0, h1);
                *(u32*)(x0 + 2 * (c + 320)) = pk(m0b, m1b);
                *(u32*)(x0 + 2 * (c + 640)) = pk(l0, l1);
                char* x1 = (char*)(g_xc[(L & 1) ^ 1] + (size_t)r1 * 960);
                split3(v10, h0, m0b, l0); split3(v11, h1, m1b, l1);
                *(u32*)(x1 + 2 * c) = pk(h0, h1);
                *(u32*)(x1 + 2 * (c + 320)) = pk(m0b, m1b);
                *(u32*)(x1 + 2 * (c + 640)) = pk(l0, l1);
            } else {
                float b0v = g_obias[c], b1v = g_obias[c + 1];
                if (c < 128) {
                    float ev = g_env[r0];
                    *(float2*)&g_sw[(size_t)r0 * 128 + c] =
                        make_float2((d[0] + b0v) * ev, (d[1] + b1v) * ev);
                } else {
                    float ev = g_env[r1];
                    *(float2*)&g_sw[(size_t)r1 * 128 + (c - 128)] =
                        make_float2((d[2] + b0v) * ev, (d[3] + b1v) * ev);
                }
            }
        }
    }
}

// ---------------- slogdet + combine ----------------
__global__ void __launch_bounds__(32) slogdetK(const float* __restrict__ wfW,
                                               float* __restrict__ out) {
    __shared__ float ldv[32], sgv[32];
    const int b = blockIdx.x, t = threadIdx.x;
    const int spin = t >> 4, d = t & 15;
    float M[8][8];
#pragma unroll
    for (int o = 0; o < 8; ++o)
#pragma unroll
        for (int e = 0; e < 8; ++e)
            M[o][e] = g_sw[(size_t)(b * 16 + spin * 8 + e) * 128 + o * 16 + d];
    float ld = 0.f, sg = 1.f;
    for (int k = 0; k < 8; ++k) {
        int piv = k;
        float mx = fabsf(M[k][k]);
        for (int i2 = k + 1; i2 < 8; ++i2) {
            float v = fabsf(M[i2][k]);
            if (v > mx) { mx = v; piv = i2; }
        }
        if (piv != k) {
            for (int j2 = 0; j2 < 8; ++j2) {
                float tt = M[k][j2]; M[k][j2] = M[piv][j2]; M[piv][j2] = tt;
            }
            sg = -sg;
        }
        float pv = M[k][k];
        ld += logf(fabsf(pv));
        if (pv < 0.f) sg = -sg;
        float inv = 1.0f / pv;
        for (int i2 = k + 1; i2 < 8; ++i2) {
            float f = M[i2][k] * inv;
            for (int j2 = k + 1; j2 < 8; ++j2)
                M[i2][j2] = fmaf(-f, M[k][j2], M[i2][j2]);
        }
    }
    ldv[t] = ld; sgv[t] = sg;
    __syncthreads();
    if (t == 0) {
        float m = -3.402823e38f, ldt[16], sgt[16];
#pragma unroll
        for (int dd = 0; dd < 16; ++dd) {
            ldt[dd] = ldv[dd] + ldv[16 + dd];
            sgt[dd] = sgv[dd] * sgv[16 + dd];
            m = fmaxf(m, ldt[dd]);
        }
        float s = 0.f;
#pragma unroll
        for (int dd = 0; dd < 16; ++dd)
            s += sgt[dd] * expf(ldt[dd] - m) * __ldg(wfW + dd);
        out[b] = logf(fabsf(s)) + m;
    }
}

extern "C" void kernel_launch(void* const* d_in, const int* in_sizes, int n_in,
                              void* d_out, int out_size) {
    const float* r   = (const float*)d_in[0];
    const float* a   = (const float*)d_in[1];
    const float* sW0 = (const float*)d_in[2];
    const float* sb0 = (const float*)d_in[3];
    const float* sW  = (const float*)d_in[4];
    const float* sb  = (const float*)d_in[5];
    const float* pW0 = (const float*)d_in[6];
    const float* pb0 = (const float*)d_in[7];
    const float* pW  = (const float*)d_in[8];
    const float* pb  = (const float*)d_in[9];
    const float* vW  = (const float*)d_in[10];
    const float* vb  = (const float*)d_in[11];
    const float* wuW = (const float*)d_in[12];
    const float* wub = (const float*)d_in[13];
    const float* wdW = (const float*)d_in[14];
    const float* wdb = (const float*)d_in[15];
    const float* wfW = (const float*)d_in[16];
    float* out = (float*)d_out;

    prepK<<<256, 256>>>(sW, vW, wuW, wdW, sb, vb, wub, wdb);
    phaseAK<<<BW, 256>>>(r, a, sW0, sb0, pW0, pb0, pW, pb);
    for (int l = 0; l < 5; ++l) {
        pudfillK<<<BW, 512>>>(l);
        gemmK<0><<<dim3(16, 2), 256>>>(l);
        if (l < 4) {
            gemmK<1><<<dim3(256, 2), 256>>>(l);
            meansK<<<BW, 256>>>((l & 1) ^ 1);
        } else {
            gemmK<2><<<dim3(256, 2), 256>>>(l);
        }
    }
    gemmK<3><<<dim3(256, 2), 256>>>(0);
    slogdetK<<<BW, 32>>>(wfW, out);
}

// round 14
// speedup vs baseline: 1.3606x; 1.3606x over previous
#include <cuda_runtime.h>
#include <cuda_bf16.h>
#include <math.h>

typedef unsigned long long u64;
typedef unsigned int u32;

#define NEL  16
#define NPV  32
#define PSTR 33
#define BW   2048
#define MR   (BW * NEL)
#define ASTG 40            // stage row stride in bf16 (80B, bank-distinct for ldmatrix)
#define STGA (128 * ASTG)  // elems per stage buffer (10240B)
#define GSM  (6 * STGA * 2)  // dynamic smem bytes = 61440

__device__ __align__(16) __nv_bfloat16 g_xc[2][(size_t)MR * 960];   // compact [h|m|l] x 320
__device__ __align__(16) float         g_s0[(size_t)MR * 256];
__device__ __align__(16) float         g_s1[(size_t)MR * 256];
__device__ __align__(16) float         g_pud[5][(size_t)BW * 1024];
__device__ __align__(16) float         g_base[BW * 256];
__device__ __align__(16) float         g_env[MR];
__device__ __align__(16) float         g_sw[(size_t)MR * 128];
__device__ __align__(16) __nv_bfloat16 g_mcat[(size_t)BW * 1536];   // compact [h|m|l] x 512
__device__ __align__(16) __nv_bfloat16 g_wscat[5][256 * 1920];      // 6 slots x 320
__device__ __align__(16) __nv_bfloat16 g_wmcat[5][256 * 3072];      // 6 slots x 512
__device__ __align__(16) __nv_bfloat16 g_worb[256 * 1536];          // 6 slots x 256
__device__ __align__(16) float         g_obias[256];
__device__ __align__(16) float         g_sbias[5][256];

__device__ __forceinline__ float fast_tanh(float x) {
    float e, r;
    asm("ex2.approx.f32 %0, %1;" : "=f"(e) : "f"(x * 2.885390082f));
    asm("rcp.approx.f32 %0, %1;" : "=f"(r) : "f"(e + 1.0f));
    return fmaf(-2.0f, r, 1.0f);
}
__device__ __forceinline__ u32 smem_u32(const void* p) {
    u32 a;
    asm("{ .reg .u64 t; cvta.to.shared.u64 t, %1; cvt.u32.u64 %0, t; }" : "=r"(a) : "l"(p));
    return a;
}
__device__ __forceinline__ void split3(float x, __nv_bfloat16& h, __nv_bfloat16& m,
                                       __nv_bfloat16& l) {
    h = __float2bfloat16(x);
    float r1 = x - __bfloat162float(h);
    m = __float2bfloat16(r1);
    float r2 = r1 - __bfloat162float(m);
    l = __float2bfloat16(r2);
}
__device__ __forceinline__ u32 pk(__nv_bfloat16 a, __nv_bfloat16 b) {
    return ((u32)__bfloat16_as_ushort(b) << 16) | (u32)__bfloat16_as_ushort(a);
}
__device__ __forceinline__ void ldmat4(u32* r, u32 addr) {
    asm volatile("ldmatrix.sync.aligned.m8n8.x4.shared.b16 {%0,%1,%2,%3}, [%4];"
                 : "=r"(r[0]), "=r"(r[1]), "=r"(r[2]), "=r"(r[3]) : "r"(addr));
}
__device__ __forceinline__ void mma16816(float* d, const u32* a, const u32* b) {
    asm volatile(
        "mma.sync.aligned.m16n8k16.row.col.f32.bf16.bf16.f32 "
        "{%0,%1,%2,%3}, {%4,%5,%6,%7}, {%8,%9}, {%0,%1,%2,%3};"
        : "+f"(d[0]), "+f"(d[1]), "+f"(d[2]), "+f"(d[3])
        : "r"(a[0]), "r"(a[1]), "r"(a[2]), "r"(a[3]), "r"(b[0]), "r"(b[1]));
}
__device__ __forceinline__ void cp16(u32 dst, const void* src) {
    asm volatile("cp.async.ca.shared.global [%0], [%1], 16;" :: "r"(dst), "l"(src));
}
#define CP_COMMIT() asm volatile("cp.async.commit_group;" ::: "memory")
#define CP_WAIT2()  asm volatile("cp.async.wait_group 2;" ::: "memory")
__device__ __forceinline__ float* sbuf(int p) { return p ? g_s1 : g_s0; }

// slot j computes A[amap[j]] * W[wver[j]]: h*h, m*h, h*m, l*h, m*m, h*l
__device__ __constant__ int c_amap[6] = {0, 1, 0, 2, 1, 0};

// ---------------- weight prep ----------------
__global__ void prepK(const float* __restrict__ sW, const float* __restrict__ vW,
                      const float* __restrict__ wuW, const float* __restrict__ wdW,
                      const float* __restrict__ sb, const float* __restrict__ vb,
                      const float* __restrict__ wub, const float* __restrict__ wdb) {
    int gt = blockIdx.x * blockDim.x + threadIdx.x, gs = gridDim.x * blockDim.x;
    for (int i = gt; i < 5 * 256 * 1920; i += gs) {
        int L = i / (256 * 1920), r2 = i % (256 * 1920), n = r2 / 1920, k = r2 % 1920;
        const float* W = (L < 4) ? sW + (size_t)L * 832 * 256 : vW;
        int slot = k / 320, km = k % 320;
        int kr = (km < 256) ? km : 512 + km;
        float v = W[(size_t)kr * 256 + n];
        __nv_bfloat16 h, m, l; split3(v, h, m, l);
        int ver = (slot == 2 || slot == 4) ? 1 : (slot == 5 ? 2 : 0);
        g_wscat[L][n * 1920 + k] = (ver == 0) ? h : (ver == 1 ? m : l);
    }
    for (int i = gt; i < 5 * 256 * 3072; i += gs) {
        int L = i / (256 * 3072), r2 = i % (256 * 3072), n = r2 / 3072, k = r2 % 3072;
        const float* W = (L < 4) ? sW + (size_t)L * 832 * 256 : vW;
        int slot = k / 512;
        int kr = 256 + (k % 512);
        float v = W[(size_t)kr * 256 + n];
        __nv_bfloat16 h, m, l; split3(v, h, m, l);
        int ver = (slot == 2 || slot == 4) ? 1 : (slot == 5 ? 2 : 0);
        g_wmcat[L][n * 3072 + k] = (ver == 0) ? h : (ver == 1 ? m : l);
    }
    for (int i = gt; i < 256 * 1536; i += gs) {
        int n = i / 1536, k = i % 1536;
        int slot = k / 256, kk = k % 256;
        float v = (n < 128) ? wuW[kk * 128 + n] : wdW[kk * 128 + (n - 128)];
        __nv_bfloat16 h, m, l; split3(v, h, m, l);
        int ver = (slot == 2 || slot == 4) ? 1 : (slot == 5 ? 2 : 0);
        g_worb[n * 1536 + k] = (ver == 0) ? h : (ver == 1 ? m : l);
    }
    for (int i = gt; i < 256; i += gs) g_obias[i] = (i < 128) ? wub[i] : wdb[i - 128];
    for (int i = gt; i < 5 * 256; i += gs) {
        int L = i >> 8, c = i & 255;
        g_sbias[L][c] = (L < 4) ? sb[L * 256 + c] : vb[c];
    }
}

__global__ void biasK(int L) {
    g_base[blockIdx.x * 256 + threadIdx.x] = g_sbias[L][threadIdx.x];
}

// ---------------- Phase A ----------------
template <int KIN, bool RES>
__device__ void pA_mm(float* p, const float* __restrict__ W, const float* __restrict__ bias,
                      float* pw, float* pbv, int tid) {
    for (int i = tid; i < KIN * NPV; i += 256) pw[i] = __ldg(W + i);
    if (tid < NPV) pbv[tid] = __ldg(bias + tid);
    __syncthreads();
    float* prow = p + tid * PSTR;
    float pin[KIN];
#pragma unroll
    for (int k = 0; k < KIN; ++k) pin[k] = prow[k];
#pragma unroll
    for (int cb = 0; cb < NPV; cb += 4) {
        float4 a = *(const float4*)(pbv + cb);
#pragma unroll
        for (int k = 0; k < KIN; ++k) {
            float4 w = *(const float4*)(pw + k * NPV + cb);
            a.x = fmaf(pin[k], w.x, a.x); a.y = fmaf(pin[k], w.y, a.y);
            a.z = fmaf(pin[k], w.z, a.z); a.w = fmaf(pin[k], w.w, a.w);
        }
        prow[cb + 0] = RES ? fast_tanh(a.x) + pin[cb + 0] : fast_tanh(a.x);
        prow[cb + 1] = RES ? fast_tanh(a.y) + pin[cb + 1] : fast_tanh(a.y);
        prow[cb + 2] = RES ? fast_tanh(a.z) + pin[cb + 2] : fast_tanh(a.z);
        prow[cb + 3] = RES ? fast_tanh(a.w) + pin[cb + 3] : fast_tanh(a.w);
    }
    __syncthreads();
}

__device__ void pA_means(float* dst, const float* p, int tid) {
    for (int idx = tid; idx < 512; idx += 256) {
        int j = idx >> 5, f = idx & 31;
        float a = 0.f, b = 0.f;
#pragma unroll
        for (int i = 0; i < 8; ++i) a += p[(i * NEL + j) * PSTR + f];
#pragma unroll
        for (int i = 8; i < NEL; ++i) b += p[(i * NEL + j) * PSTR + f];
        dst[j * 32 + f] = a * 0.125f;
        dst[512 + j * 32 + f] = b * 0.125f;
    }
    __syncthreads();
}

__global__ void __launch_bounds__(256) phaseAK(
    const float* __restrict__ r, const float* __restrict__ a,
    const float* __restrict__ sW0, const float* __restrict__ sb0,
    const float* __restrict__ pW0, const float* __restrict__ pb0,
    const float* __restrict__ pW, const float* __restrict__ pb) {
    __shared__ float p[256 * PSTR];
    __shared__ float x[256], mu0[16], md0[16], pu0[64], pd0[64];
    __shared__ float pw[1024], pbv[32], r_s[48], a_s[12];
    const int tid = threadIdx.x, b = blockIdx.x;

    if (tid < 48) r_s[tid] = r[b * 48 + tid];
    if (tid >= 64 && tid < 76) a_s[tid - 64] = a[tid - 64];
    __syncthreads();

    if (tid < 16) {
        int e = tid;
        float rx = r_s[e * 3], ry = r_s[e * 3 + 1], rz = r_s[e * 3 + 2];
        float envv = 0.f;
#pragma unroll
        for (int at = 0; at < 4; ++at) {
            float dx = rx - a_s[at * 3], dy = ry - a_s[at * 3 + 1], dz = rz - a_s[at * 3 + 2];
            float l = sqrtf(dx * dx + dy * dy + dz * dz);
            x[e * 16 + at * 4 + 0] = dx; x[e * 16 + at * 4 + 1] = dy;
            x[e * 16 + at * 4 + 2] = dz; x[e * 16 + at * 4 + 3] = l;
            envv += expf(-l);
        }
        g_env[b * 16 + e] = envv;
    }
    {
        int i = tid >> 4, j = tid & 15;
        float dx = r_s[j * 3] - r_s[i * 3];
        float dy = r_s[j * 3 + 1] - r_s[i * 3 + 1];
        float dz = r_s[j * 3 + 2] - r_s[i * 3 + 2];
        float l = (i == j) ? sqrtf(3.0f) : sqrtf(dx * dx + dy * dy + dz * dz);
        float* prow = p + tid * PSTR;
        prow[0] = dx; prow[1] = dy; prow[2] = dz; prow[3] = l;
    }
    __syncthreads();
    if (tid < 16) {
        float mu = 0.f, md = 0.f;
#pragma unroll
        for (int e = 0; e < 8; ++e) mu += x[e * 16 + tid];
#pragma unroll
        for (int e = 8; e < 16; ++e) md += x[e * 16 + tid];
        mu0[tid] = mu * 0.125f; md0[tid] = md * 0.125f;
    }
    if (tid < 128) {
        int half = tid >> 6, t2 = tid & 63, j = t2 >> 2, f = t2 & 3;
        float s = 0.f;
        if (half == 0) {
#pragma unroll
            for (int i = 0; i < 8; ++i) s += p[(i * NEL + j) * PSTR + f];
            pu0[j * 4 + f] = s * 0.125f;
        } else {
#pragma unroll
            for (int i = 8; i < 16; ++i) s += p[(i * NEL + j) * PSTR + f];
            pd0[j * 4 + f] = s * 0.125f;
        }
    }
    __syncthreads();

    {
        int c = tid;
        float acc[16];
#pragma unroll
        for (int e = 0; e < 16; ++e) acc[e] = 0.f;
        float bse = __ldg(sb0 + c);
#pragma unroll
        for (int k = 0; k < 16; ++k) {
            float w = __ldg(sW0 + k * 256 + c);
#pragma unroll
            for (int e = 0; e < 16; ++e) acc[e] = fmaf(x[e * 16 + k], w, acc[e]);
            bse = fmaf(mu0[k], __ldg(sW0 + (16 + k) * 256 + c), bse);
            bse = fmaf(md0[k], __ldg(sW0 + (32 + k) * 256 + c), bse);
        }
#pragma unroll
        for (int f = 0; f < 4; ++f) {
            float wpu = __ldg(sW0 + (48 + f) * 256 + c);
            float wpd = __ldg(sW0 + (52 + f) * 256 + c);
#pragma unroll
            for (int e = 0; e < 16; ++e)
                acc[e] = fmaf(pu0[e * 4 + f], wpu, fmaf(pd0[e * 4 + f], wpd, acc[e]));
        }
        float mu = 0.f, md = 0.f;
        __nv_bfloat16 h, m, l;
#pragma unroll
        for (int e = 0; e < 16; ++e) {
            float sv = fast_tanh(acc[e] + bse);
            if (e < 8) mu += sv; else md += sv;
            g_s0[(size_t)(b * 16 + e) * 256 + c] = sv;
            split3(sv, h, m, l);
            __nv_bfloat16* xr = g_xc[0] + (size_t)(b * 16 + e) * 960;
            xr[c] = h; xr[320 + c] = m; xr[640 + c] = l;
        }
        __nv_bfloat16* mr = g_mcat + (size_t)b * 1536;
        split3(mu * 0.125f, h, m, l); mr[c] = h; mr[512 + c] = m; mr[1024 + c] = l;
        split3(md * 0.125f, h, m, l); mr[256 + c] = h; mr[768 + c] = m; mr[1280 + c] = l;
    }

    pA_mm<4, false>(p, pW0, pb0, pw, pbv, tid);
    pA_means(&g_pud[0][(size_t)b * 1024], p, tid);
#pragma unroll 1
    for (int i = 0; i < 4; ++i) {
        pA_mm<32, true>(p, pW + i * 1024, pb + i * 32, pw, pbv, tid);
        pA_means(&g_pud[i + 1][(size_t)b * 1024], p, tid);
    }
}

__global__ void pudfillK(int L) {
    int i = blockIdx.x * blockDim.x + threadIdx.x;
    int b = i >> 9, t = i & 511, e = t >> 5, f = t & 31;
    float vu = g_pud[L][(size_t)b * 1024 + e * 32 + f];
    float vd = g_pud[L][(size_t)b * 1024 + 512 + e * 32 + f];
    __nv_bfloat16 hu, mu, lu, hd, md, ld;
    split3(vu, hu, mu, lu); split3(vd, hd, md, ld);
    __nv_bfloat16* xr = g_xc[L & 1] + (size_t)(b * 16 + e) * 960;
    xr[256 + f] = hu; xr[288 + f] = hd;
    xr[576 + f] = mu; xr[608 + f] = md;
    xr[896 + f] = lu; xr[928 + f] = ld;
}

__global__ void meansK(int par) {
    int b = blockIdx.x, c = threadIdx.x;
    const float* s = sbuf(par) + (size_t)b * 16 * 256;
    float mu = 0.f, md = 0.f;
#pragma unroll
    for (int e = 0; e < 8; ++e) mu += s[e * 256 + c];
#pragma unroll
    for (int e = 8; e < 16; ++e) md += s[e * 256 + c];
    __nv_bfloat16 h, m, l;
    __nv_bfloat16* mr = g_mcat + (size_t)b * 1536;
    split3(mu * 0.125f, h, m, l); mr[c] = h; mr[512 + c] = m; mr[1024 + c] = l;
    split3(md * 0.125f, h, m, l); mr[256 + c] = h; mr[768 + c] = m; mr[1280 + c] = l;
}

// ---------------- cp.async-pipelined mma.sync GEMM ----------------
// CTA 128x128, warp 32x64; 3-stage pipeline, 32-elem k-stages, dynamic smem.
// MODE 0: base split-K (gridDim.z=6 slots), epilogue atomicAdd into g_base(bias-preset)
// MODE 1: s-res layer   MODE 2: final layer   MODE 3: orbitals
template <int MODE>
__global__ void __launch_bounds__(256, 2) gemmK(int L) {
    extern __shared__ __nv_bfloat16 smg[];
    const u32 sb_ = smem_u32(smg);
    const int tid = threadIdx.x, lane = tid & 31, warp = tid >> 5;
    const int wm = warp & 3, wn = warp >> 2;
    const int gid = lane >> 2, tig = lane & 3;
    const int z = blockIdx.z;

    const __nv_bfloat16 *A, *B;
    int lda, ldb, NS;
    if (MODE == 0)      { A = g_mcat;      B = g_wmcat[L]; lda = 1536; ldb = 3072; NS = 16; }
    else if (MODE == 3) { A = g_xc[1];     B = g_worb;     lda = 960;  ldb = 1536; NS = 48; }
    else                { A = g_xc[L & 1]; B = g_wscat[L]; lda = 960;  ldb = 1920; NS = 60; }
    const int m0 = blockIdx.x * 128, n0 = blockIdx.y * 128;
    const int lrow = tid >> 1, lhalf = tid & 1;

    float acc[2][8][4];
#pragma unroll
    for (int i = 0; i < 2; ++i)
#pragma unroll
        for (int j = 0; j < 8; ++j)
#pragma unroll
            for (int k = 0; k < 4; ++k) acc[i][j][k] = 0.f;

    // stage t -> A k-offset (elems) and B k-offset (elems)
    auto aoff = [&](int t) -> int {
        if (MODE == 0) return c_amap[z] * 512 + t * 32;
        if (MODE == 3) { int sl = t >> 3; return c_amap[sl] * 320 + (t & 7) * 32; }
        int sl = t / 10; return c_amap[sl] * 320 + (t - sl * 10) * 32;
    };
    auto boff = [&](int t) -> int {
        return (MODE == 0) ? (z * 512 + t * 32) : t * 32;
    };

    auto load_stage = [&](int t, int bs) {
        const char* as = (const char*)(A + (size_t)(m0 + lrow) * lda + aoff(t)) + lhalf * 32;
        u32 ad = sb_ + (bs * STGA + lrow * ASTG + lhalf * 16) * 2;
        cp16(ad, as); cp16(ad + 16, as + 16);
        const char* bsc = (const char*)(B + (size_t)(n0 + lrow) * ldb + boff(t)) + lhalf * 32;
        u32 bd = sb_ + ((3 + bs) * STGA + lrow * ASTG + lhalf * 16) * 2;
        cp16(bd, bsc); cp16(bd + 16, bsc + 16);
    };

    load_stage(0, 0); CP_COMMIT();
    load_stage(1, 1); CP_COMMIT();

#pragma unroll 1
    for (int s = 0; s < NS; ++s) {
        if (s + 2 < NS) load_stage(s + 2, (s + 2) % 3);
        CP_COMMIT();
        CP_WAIT2();
        __syncthreads();
        const int bs = s % 3;
        const u32 abase = sb_ + (bs * STGA) * 2;
        const u32 bbase = sb_ + ((3 + bs) * STGA) * 2;
#pragma unroll
        for (int j = 0; j < 2; ++j) {
            const int kb = j * 32;
            u32 af[2][4], bq[4][4];
            ldmat4(af[0], abase + (wm * 32 + (lane & 15)) * 80 + kb + (lane >> 4) * 16);
            ldmat4(af[1], abase + (wm * 32 + 16 + (lane & 15)) * 80 + kb + (lane >> 4) * 16);
#pragma unroll
            for (int q = 0; q < 4; ++q)
                ldmat4(bq[q], bbase + (wn * 64 + q * 16 + (lane & 7) + ((lane >> 4) << 3)) * 80
                              + kb + ((lane >> 3) & 1) * 16);
#pragma unroll
            for (int mt = 0; mt < 2; ++mt)
#pragma unroll
                for (int nt = 0; nt < 8; ++nt)
                    mma16816(acc[mt][nt], af[mt], &bq[nt >> 1][(nt & 1) * 2]);
        }
        __syncthreads();
    }

    // epilogue
    const int rb = m0 + wm * 32, cb0 = n0 + wn * 64;
#pragma unroll
    for (int mt = 0; mt < 2; ++mt) {
        const int r0 = rb + mt * 16 + gid, r1 = r0 + 8;
#pragma unroll
        for (int nt = 0; nt < 8; ++nt) {
            const int c = cb0 + nt * 8 + tig * 2;
            float* d = acc[mt][nt];
            if (MODE == 0) {
                atomicAdd(&g_base[(size_t)r0 * 256 + c], d[0]);
                atomicAdd(&g_base[(size_t)r0 * 256 + c + 1], d[1]);
                atomicAdd(&g_base[(size_t)r1 * 256 + c], d[2]);
                atomicAdd(&g_base[(size_t)r1 * 256 + c + 1], d[3]);
            } else if (MODE == 1 || MODE == 2) {
                const float* bas = g_base + (size_t)(r0 >> 4) * 256;
                float v00 = fast_tanh(d[0] + bas[c]);
                float v01 = fast_tanh(d[1] + bas[c + 1]);
                float v10 = fast_tanh(d[2] + bas[c]);
                float v11 = fast_tanh(d[3] + bas[c + 1]);
                if (MODE == 1) {
                    const float* rs = sbuf(L & 1);
                    float* so = sbuf((L & 1) ^ 1);
                    float2 q0 = *(const float2*)&rs[(size_t)r0 * 256 + c];
                    float2 q1 = *(const float2*)&rs[(size_t)r1 * 256 + c];
                    v00 += q0.x; v01 += q0.y; v10 += q1.x; v11 += q1.y;
                    *(float2*)&so[(size_t)r0 * 256 + c] = make_float2(v00, v01);
                    *(float2*)&so[(size_t)r1 * 256 + c] = make_float2(v10, v11);
                }
                __nv_bfloat16 h0, m0b, l0, h1, m1b, l1;
                char* x0 = (char*)(g_xc[(L & 1) ^ 1] + (size_t)r0 * 960);
                split3(v00, h0, m0b, l0); split3(v01, h1, m1b, l1);
                *(u32*)(x0 + 2 * c) = pk(h0, h1);
                *(u32*)(x0 + 2 * (c + 320)) = pk(m0b, m1b);
                *(u32*)(x0 + 2 * (c + 640)) = pk(l0, l1);
                char* x1 = (char*)(g_xc[(L & 1) ^ 1] + (size_t)r1 * 960);
                split3(v10, h0, m0b, l0); split3(v11, h1, m1b, l1);
                *(u32*)(x1 + 2 * c) = pk(h0, h1);
                *(u32*)(x1 + 2 * (c + 320)) = pk(m0b, m1b);
                *(u32*)(x1 + 2 * (c + 640)) = pk(l0, l1);
            } else {
                float b0v = g_obias[c], b1v = g_obias[c + 1];
                if (c < 128) {
                    float ev = g_env[r0];
                    *(float2*)&g_sw[(size_t)r0 * 128 + c] =
                        make_float2((d[0] + b0v) * ev, (d[1] + b1v) * ev);
                } else {
                    float ev = g_env[r1];
                    *(float2*)&g_sw[(size_t)r1 * 128 + (c - 128)] =
                        make_float2((d[2] + b0v) * ev, (d[3] + b1v) * ev);
                }
            }
        }
    }
}

// ---------------- slogdet + combine ----------------
__global__ void __launch_bounds__(32) slogdetK(const float* __restrict__ wfW,
                                               float* __restrict__ out) {
    __shared__ float ldv[32], sgv[32];
    const int b = blockIdx.x, t = threadIdx.x;
    const int spin = t >> 4, d = t & 15;
    float M[8][8];
#pragma unroll
    for (int o = 0; o < 8; ++o)
#pragma unroll
        for (int e = 0; e < 8; ++e)
            M[o][e] = g_sw[(size_t)(b * 16 + spin * 8 + e) * 128 + o * 16 + d];
    float ld = 0.f, sg = 1.f;
    for (int k = 0; k < 8; ++k) {
        int piv = k;
        float mx = fabsf(M[k][k]);
        for (int i2 = k + 1; i2 < 8; ++i2) {
            float v = fabsf(M[i2][k]);
            if (v > mx) { mx = v; piv = i2; }
        }
        if (piv != k) {
            for (int j2 = 0; j2 < 8; ++j2) {
                float tt = M[k][j2]; M[k][j2] = M[piv][j2]; M[piv][j2] = tt;
            }
            sg = -sg;
        }
        float pv = M[k][k];
        ld += logf(fabsf(pv));
        if (pv < 0.f) sg = -sg;
        float inv = 1.0f / pv;
        for (int i2 = k + 1; i2 < 8; ++i2) {
            float f = M[i2][k] * inv;
            for (int j2 = k + 1; j2 < 8; ++j2)
                M[i2][j2] = fmaf(-f, M[k][j2], M[i2][j2]);
        }
    }
    ldv[t] = ld; sgv[t] = sg;
    __syncthreads();
    if (t == 0) {
        float m = -3.402823e38f, ldt[16], sgt[16];
#pragma unroll
        for (int dd = 0; dd < 16; ++dd) {
            ldt[dd] = ldv[dd] + ldv[16 + dd];
            sgt[dd] = sgv[dd] * sgv[16 + dd];
            m = fmaxf(m, ldt[dd]);
        }
        float s = 0.f;
#pragma unroll
        for (int dd = 0; dd < 16; ++dd)
            s += sgt[dd] * expf(ldt[dd] - m) * __ldg(wfW + dd);
        out[b] = logf(fabsf(s)) + m;
    }
}

extern "C" void kernel_launch(void* const* d_in, const int* in_sizes, int n_in,
                              void* d_out, int out_size) {
    const float* r   = (const float*)d_in[0];
    const float* a   = (const float*)d_in[1];
    const float* sW0 = (const float*)d_in[2];
    const float* sb0 = (const float*)d_in[3];
    const float* sW  = (const float*)d_in[4];
    const float* sb  = (const float*)d_in[5];
    const float* pW0 = (const float*)d_in[6];
    const float* pb0 = (const float*)d_in[7];
    const float* pW  = (const float*)d_in[8];
    const float* pb  = (const float*)d_in[9];
    const float* vW  = (const float*)d_in[10];
    const float* vb  = (const float*)d_in[11];
    const float* wuW = (const float*)d_in[12];
    const float* wub = (const float*)d_in[13];
    const float* wdW = (const float*)d_in[14];
    const float* wdb = (const float*)d_in[15];
    const float* wfW = (const float*)d_in[16];
    float* out = (float*)d_out;

    cudaFuncSetAttribute(gemmK<0>, cudaFuncAttributeMaxDynamicSharedMemorySize, GSM);
    cudaFuncSetAttribute(gemmK<1>, cudaFuncAttributeMaxDynamicSharedMemorySize, GSM);
    cudaFuncSetAttribute(gemmK<2>, cudaFuncAttributeMaxDynamicSharedMemorySize, GSM);
    cudaFuncSetAttribute(gemmK<3>, cudaFuncAttributeMaxDynamicSharedMemorySize, GSM);

    prepK<<<256, 256>>>(sW, vW, wuW, wdW, sb, vb, wub, wdb);
    phaseAK<<<BW, 256>>>(r, a, sW0, sb0, pW0, pb0, pW, pb);
    for (int l = 0; l < 5; ++l) {
        biasK<<<BW, 256>>>(l);
        pudfillK<<<BW, 512>>>(l);
        gemmK<0><<<dim3(16, 2, 6), 256, GSM>>>(l);
        if (l < 4) {
            gemmK<1><<<dim3(256, 2), 256, GSM>>>(l);
            meansK<<<BW, 256>>>((l & 1) ^ 1);
        } else {
            gemmK<2><<<dim3(256, 2), 256, GSM>>>(l);
        }
    }
    gemmK<3><<<dim3(256, 2), 256, GSM>>>(0);
    slogdetK<<<BW, 32>>>(wfW, out);
}

// round 15
// speedup vs baseline: 2.0314x; 1.4931x over previous
#include <cuda_runtime.h>
#include <cuda_fp16.h>
#include <math.h>

typedef unsigned long long u64;
typedef unsigned int u32;

#define NEL  16
#define NPV  32
#define PSTR 33
#define BW   2048
#define MR   (BW * NEL)
#define ASTG 40            // stage row stride in fp16 (80B, bank-distinct for ldmatrix)
#define STGA (128 * ASTG)  // elems per stage buffer (10240B)
#define GSM  (8 * STGA * 2)  // 4 A-stages + 4 B-stages = 81920 bytes

__device__ __align__(16) __half g_xc[2][(size_t)MR * 640];   // compact [h|m] x 320
__device__ __align__(16) float  g_s0[(size_t)MR * 256];
__device__ __align__(16) float  g_s1[(size_t)MR * 256];
__device__ __align__(16) float  g_pud[5][(size_t)BW * 1024];
__device__ __align__(16) float  g_base6[3][(size_t)BW * 256];
__device__ __align__(16) float  g_env[MR];
__device__ __align__(16) float  g_sw[(size_t)MR * 128];
__device__ __align__(16) __half g_mcat[(size_t)BW * 1024];   // compact [h|m] x 512
__device__ __align__(16) __half g_wscat[5][256 * 960];       // 3 slots x 320: {wh,wh,wm}
__device__ __align__(16) __half g_wmcat[5][256 * 1536];      // 3 slots x 512
__device__ __align__(16) __half g_worb[256 * 768];           // 3 slots x 256
__device__ __align__(16) float  g_obias[256];
__device__ __align__(16) float  g_sbias[5][256];

__device__ __forceinline__ float fast_tanh(float x) {
    float e, r;
    asm("ex2.approx.f32 %0, %1;" : "=f"(e) : "f"(x * 2.885390082f));
    asm("rcp.approx.f32 %0, %1;" : "=f"(r) : "f"(e + 1.0f));
    return fmaf(-2.0f, r, 1.0f);
}
__device__ __forceinline__ u32 smem_u32(const void* p) {
    u32 a;
    asm("{ .reg .u64 t; cvta.to.shared.u64 t, %1; cvt.u32.u64 %0, t; }" : "=r"(a) : "l"(p));
    return a;
}
// two-way fp16 split: x ~= h + m to ~22 bits
__device__ __forceinline__ void split2(float x, __half& h, __half& m) {
    h = __float2half_rn(x);
    m = __float2half_rn(x - __half2float(h));
}
__device__ __forceinline__ u32 pkh(__half a, __half b) {
    return ((u32)__half_as_ushort(b) << 16) | (u32)__half_as_ushort(a);
}
__device__ __forceinline__ void ldmat4(u32* r, u32 addr) {
    asm volatile("ldmatrix.sync.aligned.m8n8.x4.shared.b16 {%0,%1,%2,%3}, [%4];"
                 : "=r"(r[0]), "=r"(r[1]), "=r"(r[2]), "=r"(r[3]) : "r"(addr));
}
__device__ __forceinline__ void mma16816(float* d, const u32* a, const u32* b) {
    asm volatile(
        "mma.sync.aligned.m16n8k16.row.col.f32.f16.f16.f32 "
        "{%0,%1,%2,%3}, {%4,%5,%6,%7}, {%8,%9}, {%0,%1,%2,%3};"
        : "+f"(d[0]), "+f"(d[1]), "+f"(d[2]), "+f"(d[3])
        : "r"(a[0]), "r"(a[1]), "r"(a[2]), "r"(a[3]), "r"(b[0]), "r"(b[1]));
}
__device__ __forceinline__ void cp16(u32 dst, const void* src) {
    asm volatile("cp.async.ca.shared.global [%0], [%1], 16;" :: "r"(dst), "l"(src));
}
#define CP_COMMIT() asm volatile("cp.async.commit_group;" ::: "memory")
#define CP_WAIT2()  asm volatile("cp.async.wait_group 2;" ::: "memory")
__device__ __forceinline__ float* sbuf(int p) { return p ? g_s1 : g_s0; }

// slot j computes A[amap[j]] * W[wver[j]]: h*wh, m*wh, h*wm
__device__ __constant__ int c_amap[3] = {0, 1, 0};

// ---------------- weight prep ----------------
__global__ void prepK(const float* __restrict__ sW, const float* __restrict__ vW,
                      const float* __restrict__ wuW, const float* __restrict__ wdW,
                      const float* __restrict__ sb, const float* __restrict__ vb,
                      const float* __restrict__ wub, const float* __restrict__ wdb) {
    int gt = blockIdx.x * blockDim.x + threadIdx.x, gs = gridDim.x * blockDim.x;
    for (int i = gt; i < 5 * 256 * 960; i += gs) {
        int L = i / (256 * 960), r2 = i % (256 * 960), n = r2 / 960, k = r2 % 960;
        const float* W = (L < 4) ? sW + (size_t)L * 832 * 256 : vW;
        int slot = k / 320, km = k % 320;
        int kr = (km < 256) ? km : 512 + km;
        float v = W[(size_t)kr * 256 + n];
        __half h, m; split2(v, h, m);
        g_wscat[L][n * 960 + k] = (slot < 2) ? h : m;
    }
    for (int i = gt; i < 5 * 256 * 1536; i += gs) {
        int L = i / (256 * 1536), r2 = i % (256 * 1536), n = r2 / 1536, k = r2 % 1536;
        const float* W = (L < 4) ? sW + (size_t)L * 832 * 256 : vW;
        int slot = k / 512;
        int kr = 256 + (k % 512);
        float v = W[(size_t)kr * 256 + n];
        __half h, m; split2(v, h, m);
        g_wmcat[L][n * 1536 + k] = (slot < 2) ? h : m;
    }
    for (int i = gt; i < 256 * 768; i += gs) {
        int n = i / 768, k = i % 768;
        int slot = k / 256, kk = k % 256;
        float v = (n < 128) ? wuW[kk * 128 + n] : wdW[kk * 128 + (n - 128)];
        __half h, m; split2(v, h, m);
        g_worb[n * 768 + k] = (slot < 2) ? h : m;
    }
    for (int i = gt; i < 256; i += gs) g_obias[i] = (i < 128) ? wub[i] : wdb[i - 128];
    for (int i = gt; i < 5 * 256; i += gs) {
        int L = i >> 8, c = i & 255;
        g_sbias[L][c] = (L < 4) ? sb[L * 256 + c] : vb[c];
    }
}

// ---------------- Phase A ----------------
template <int KIN, bool RES>
__device__ void pA_mm(float* p, const float* __restrict__ W, const float* __restrict__ bias,
                      float* pw, float* pbv, int tid) {
    for (int i = tid; i < KIN * NPV; i += 256) pw[i] = __ldg(W + i);
    if (tid < NPV) pbv[tid] = __ldg(bias + tid);
    __syncthreads();
    float* prow = p + tid * PSTR;
    float pin[KIN];
#pragma unroll
    for (int k = 0; k < KIN; ++k) pin[k] = prow[k];
#pragma unroll
    for (int cb = 0; cb < NPV; cb += 4) {
        float4 a = *(const float4*)(pbv + cb);
#pragma unroll
        for (int k = 0; k < KIN; ++k) {
            float4 w = *(const float4*)(pw + k * NPV + cb);
            a.x = fmaf(pin[k], w.x, a.x); a.y = fmaf(pin[k], w.y, a.y);
            a.z = fmaf(pin[k], w.z, a.z); a.w = fmaf(pin[k], w.w, a.w);
        }
        prow[cb + 0] = RES ? fast_tanh(a.x) + pin[cb + 0] : fast_tanh(a.x);
        prow[cb + 1] = RES ? fast_tanh(a.y) + pin[cb + 1] : fast_tanh(a.y);
        prow[cb + 2] = RES ? fast_tanh(a.z) + pin[cb + 2] : fast_tanh(a.z);
        prow[cb + 3] = RES ? fast_tanh(a.w) + pin[cb + 3] : fast_tanh(a.w);
    }
    __syncthreads();
}

__device__ void pA_means(float* dst, const float* p, int tid) {
    for (int idx = tid; idx < 512; idx += 256) {
        int j = idx >> 5, f = idx & 31;
        float a = 0.f, b = 0.f;
#pragma unroll
        for (int i = 0; i < 8; ++i) a += p[(i * NEL + j) * PSTR + f];
#pragma unroll
        for (int i = 8; i < NEL; ++i) b += p[(i * NEL + j) * PSTR + f];
        dst[j * 32 + f] = a * 0.125f;
        dst[512 + j * 32 + f] = b * 0.125f;
    }
    __syncthreads();
}

__global__ void __launch_bounds__(256) phaseAK(
    const float* __restrict__ r, const float* __restrict__ a,
    const float* __restrict__ sW0, const float* __restrict__ sb0,
    const float* __restrict__ pW0, const float* __restrict__ pb0,
    const float* __restrict__ pW, const float* __restrict__ pb) {
    __shared__ float p[256 * PSTR];
    __shared__ float x[256], mu0[16], md0[16], pu0[64], pd0[64];
    __shared__ float pw[1024], pbv[32], r_s[48], a_s[12];
    const int tid = threadIdx.x, b = blockIdx.x;

    if (tid < 48) r_s[tid] = r[b * 48 + tid];
    if (tid >= 64 && tid < 76) a_s[tid - 64] = a[tid - 64];
    __syncthreads();

    if (tid < 16) {
        int e = tid;
        float rx = r_s[e * 3], ry = r_s[e * 3 + 1], rz = r_s[e * 3 + 2];
        float envv = 0.f;
#pragma unroll
        for (int at = 0; at < 4; ++at) {
            float dx = rx - a_s[at * 3], dy = ry - a_s[at * 3 + 1], dz = rz - a_s[at * 3 + 2];
            float l = sqrtf(dx * dx + dy * dy + dz * dz);
            x[e * 16 + at * 4 + 0] = dx; x[e * 16 + at * 4 + 1] = dy;
            x[e * 16 + at * 4 + 2] = dz; x[e * 16 + at * 4 + 3] = l;
            envv += expf(-l);
        }
        g_env[b * 16 + e] = envv;
    }
    {
        int i = tid >> 4, j = tid & 15;
        float dx = r_s[j * 3] - r_s[i * 3];
        float dy = r_s[j * 3 + 1] - r_s[i * 3 + 1];
        float dz = r_s[j * 3 + 2] - r_s[i * 3 + 2];
        float l = (i == j) ? sqrtf(3.0f) : sqrtf(dx * dx + dy * dy + dz * dz);
        float* prow = p + tid * PSTR;
        prow[0] = dx; prow[1] = dy; prow[2] = dz; prow[3] = l;
    }
    __syncthreads();
    if (tid < 16) {
        float mu = 0.f, md = 0.f;
#pragma unroll
        for (int e = 0; e < 8; ++e) mu += x[e * 16 + tid];
#pragma unroll
        for (int e = 8; e < 16; ++e) md += x[e * 16 + tid];
        mu0[tid] = mu * 0.125f; md0[tid] = md * 0.125f;
    }
    if (tid < 128) {
        int half = tid >> 6, t2 = tid & 63, j = t2 >> 2, f = t2 & 3;
        float s = 0.f;
        if (half == 0) {
#pragma unroll
            for (int i = 0; i < 8; ++i) s += p[(i * NEL + j) * PSTR + f];
            pu0[j * 4 + f] = s * 0.125f;
        } else {
#pragma unroll
            for (int i = 8; i < 16; ++i) s += p[(i * NEL + j) * PSTR + f];
            pd0[j * 4 + f] = s * 0.125f;
        }
    }
    __syncthreads();

    {
        int c = tid;
        float acc[16];
#pragma unroll
        for (int e = 0; e < 16; ++e) acc[e] = 0.f;
        float bse = __ldg(sb0 + c);
#pragma unroll
        for (int k = 0; k < 16; ++k) {
            float w = __ldg(sW0 + k * 256 + c);
#pragma unroll
            for (int e = 0; e < 16; ++e) acc[e] = fmaf(x[e * 16 + k], w, acc[e]);
            bse = fmaf(mu0[k], __ldg(sW0 + (16 + k) * 256 + c), bse);
            bse = fmaf(md0[k], __ldg(sW0 + (32 + k) * 256 + c), bse);
        }
#pragma unroll
        for (int f = 0; f < 4; ++f) {
            float wpu = __ldg(sW0 + (48 + f) * 256 + c);
            float wpd = __ldg(sW0 + (52 + f) * 256 + c);
#pragma unroll
            for (int e = 0; e < 16; ++e)
                acc[e] = fmaf(pu0[e * 4 + f], wpu, fmaf(pd0[e * 4 + f], wpd, acc[e]));
        }
        float mu = 0.f, md = 0.f;
        __half h, m;
#pragma unroll
        for (int e = 0; e < 16; ++e) {
            float sv = fast_tanh(acc[e] + bse);
            if (e < 8) mu += sv; else md += sv;
            g_s0[(size_t)(b * 16 + e) * 256 + c] = sv;
            split2(sv, h, m);
            __half* xr = g_xc[0] + (size_t)(b * 16 + e) * 640;
            xr[c] = h; xr[320 + c] = m;
        }
        __half* mr = g_mcat + (size_t)b * 1024;
        split2(mu * 0.125f, h, m); mr[c] = h; mr[512 + c] = m;
        split2(md * 0.125f, h, m); mr[256 + c] = h; mr[768 + c] = m;
    }

    pA_mm<4, false>(p, pW0, pb0, pw, pbv, tid);
    pA_means(&g_pud[0][(size_t)b * 1024], p, tid);
#pragma unroll 1
    for (int i = 0; i < 4; ++i) {
        pA_mm<32, true>(p, pW + i * 1024, pb + i * 32, pw, pbv, tid);
        pA_means(&g_pud[i + 1][(size_t)b * 1024], p, tid);
    }
}

__global__ void pudfillK(int L) {
    int i = blockIdx.x * blockDim.x + threadIdx.x;
    int b = i >> 9, t = i & 511, e = t >> 5, f = t & 31;
    float vu = g_pud[L][(size_t)b * 1024 + e * 32 + f];
    float vd = g_pud[L][(size_t)b * 1024 + 512 + e * 32 + f];
    __half hu, mu, hd, md;
    split2(vu, hu, mu); split2(vd, hd, md);
    __half* xr = g_xc[L & 1] + (size_t)(b * 16 + e) * 640;
    xr[256 + f] = hu; xr[288 + f] = hd;
    xr[576 + f] = mu; xr[608 + f] = md;
}

__global__ void meansK(int par) {
    int b = blockIdx.x, c = threadIdx.x;
    const float* s = sbuf(par) + (size_t)b * 16 * 256;
    float mu = 0.f, md = 0.f;
#pragma unroll
    for (int e = 0; e < 8; ++e) mu += s[e * 256 + c];
#pragma unroll
    for (int e = 8; e < 16; ++e) md += s[e * 256 + c];
    __half h, m;
    __half* mr = g_mcat + (size_t)b * 1024;
    split2(mu * 0.125f, h, m); mr[c] = h; mr[512 + c] = m;
    split2(md * 0.125f, h, m); mr[256 + c] = h; mr[768 + c] = m;
}

// ---------------- cp.async-pipelined mma.sync GEMM (fp16x3) ----------------
// CTA 128x128, warp 32x64; 4-stage pipeline, 32-elem k-stages, ONE sync per stage.
// MODE 0: base split-K (z=0..2) -> g_base6[z] (plain stores)
// MODE 1: s-res layer   MODE 2: final layer   MODE 3: orbitals
template <int MODE>
__global__ void __launch_bounds__(256, 2) gemmK(int L) {
    extern __shared__ __half smg[];
    const u32 sb_ = smem_u32(smg);
    const int tid = threadIdx.x, lane = tid & 31, warp = tid >> 5;
    const int wm = warp & 3, wn = warp >> 2;
    const int gid = lane >> 2, tig = lane & 3;
    const int z = blockIdx.z;

    const __half *A, *B;
    int lda, ldb, NS;
    if (MODE == 0)      { A = g_mcat;      B = g_wmcat[L]; lda = 1024; ldb = 1536; NS = 16; }
    else if (MODE == 3) { A = g_xc[1];     B = g_worb;     lda = 640;  ldb = 768;  NS = 24; }
    else                { A = g_xc[L & 1]; B = g_wscat[L]; lda = 640;  ldb = 960;  NS = 30; }
    const int m0 = blockIdx.x * 128, n0 = blockIdx.y * 128;
    const int lrow = tid >> 1, lhalf = tid & 1;

    float acc[2][8][4];
#pragma unroll
    for (int i = 0; i < 2; ++i)
#pragma unroll
        for (int j = 0; j < 8; ++j)
#pragma unroll
            for (int k = 0; k < 4; ++k) acc[i][j][k] = 0.f;

    auto aoff = [&](int t) -> int {
        if (MODE == 0) return c_amap[z] * 512 + t * 32;
        if (MODE == 3) { int sl = t >> 3; return c_amap[sl] * 320 + (t & 7) * 32; }
        int sl = t / 10; return c_amap[sl] * 320 + (t - sl * 10) * 32;
    };
    auto boff = [&](int t) -> int {
        return (MODE == 0) ? (z * 512 + t * 32) : t * 32;
    };

    auto load_stage = [&](int t, int bs) {
        const char* as = (const char*)(A + (size_t)(m0 + lrow) * lda + aoff(t)) + lhalf * 32;
        u32 ad = sb_ + (bs * STGA + lrow * ASTG + lhalf * 16) * 2;
        cp16(ad, as); cp16(ad + 16, as + 16);
        const char* bsc = (const char*)(B + (size_t)(n0 + lrow) * ldb + boff(t)) + lhalf * 32;
        u32 bd = sb_ + ((4 + bs) * STGA + lrow * ASTG + lhalf * 16) * 2;
        cp16(bd, bsc); cp16(bd + 16, bsc + 16);
    };

    load_stage(0, 0); CP_COMMIT();
    load_stage(1, 1); CP_COMMIT();
    load_stage(2, 2); CP_COMMIT();

#pragma unroll 1
    for (int s = 0; s < NS; ++s) {
        CP_WAIT2();
        __syncthreads();
        if (s + 3 < NS) load_stage(s + 3, (s + 3) & 3);
        CP_COMMIT();
        const int bs = s & 3;
        const u32 abase = sb_ + (bs * STGA) * 2;
        const u32 bbase = sb_ + ((4 + bs) * STGA) * 2;
#pragma unroll
        for (int j = 0; j < 2; ++j) {
            const int kb = j * 32;
            u32 af[2][4], bq[4][4];
            ldmat4(af[0], abase + (wm * 32 + (lane & 15)) * 80 + kb + (lane >> 4) * 16);
            ldmat4(af[1], abase + (wm * 32 + 16 + (lane & 15)) * 80 + kb + (lane >> 4) * 16);
#pragma unroll
            for (int q = 0; q < 4; ++q)
                ldmat4(bq[q], bbase + (wn * 64 + q * 16 + (lane & 7) + ((lane >> 4) << 3)) * 80
                              + kb + ((lane >> 3) & 1) * 16);
#pragma unroll
            for (int mt = 0; mt < 2; ++mt)
#pragma unroll
                for (int nt = 0; nt < 8; ++nt)
                    mma16816(acc[mt][nt], af[mt], &bq[nt >> 1][(nt & 1) * 2]);
        }
    }

    // epilogue
    const int rb = m0 + wm * 32, cb0 = n0 + wn * 64;
#pragma unroll
    for (int mt = 0; mt < 2; ++mt) {
        const int r0 = rb + mt * 16 + gid, r1 = r0 + 8;
#pragma unroll
        for (int nt = 0; nt < 8; ++nt) {
            const int c = cb0 + nt * 8 + tig * 2;
            float* d = acc[mt][nt];
            if (MODE == 0) {
                float* b6 = g_base6[z];
                *(float2*)&b6[(size_t)r0 * 256 + c] = make_float2(d[0], d[1]);
                *(float2*)&b6[(size_t)r1 * 256 + c] = make_float2(d[2], d[3]);
            } else if (MODE == 1 || MODE == 2) {
                size_t bi = (size_t)(r0 >> 4) * 256;
                float bc0 = g_base6[0][bi + c] + g_base6[1][bi + c] + g_base6[2][bi + c]
                          + g_sbias[L][c];
                float bc1 = g_base6[0][bi + c + 1] + g_base6[1][bi + c + 1]
                          + g_base6[2][bi + c + 1] + g_sbias[L][c + 1];
                float v00 = fast_tanh(d[0] + bc0);
                float v01 = fast_tanh(d[1] + bc1);
                float v10 = fast_tanh(d[2] + bc0);
                float v11 = fast_tanh(d[3] + bc1);
                if (MODE == 1) {
                    const float* rs = sbuf(L & 1);
                    float* so = sbuf((L & 1) ^ 1);
                    float2 q0 = *(const float2*)&rs[(size_t)r0 * 256 + c];
                    float2 q1 = *(const float2*)&rs[(size_t)r1 * 256 + c];
                    v00 += q0.x; v01 += q0.y; v10 += q1.x; v11 += q1.y;
                    *(float2*)&so[(size_t)r0 * 256 + c] = make_float2(v00, v01);
                    *(float2*)&so[(size_t)r1 * 256 + c] = make_float2(v10, v11);
                }
                __half h0, m0h, h1, m1h;
                char* x0 = (char*)(g_xc[(L & 1) ^ 1] + (size_t)r0 * 640);
                split2(v00, h0, m0h); split2(v01, h1, m1h);
                *(u32*)(x0 + 2 * c) = pkh(h0, h1);
                *(u32*)(x0 + 2 * (c + 320)) = pkh(m0h, m1h);
                char* x1 = (char*)(g_xc[(L & 1) ^ 1] + (size_t)r1 * 640);
                split2(v10, h0, m0h); split2(v11, h1, m1h);
                *(u32*)(x1 + 2 * c) = pkh(h0, h1);
                *(u32*)(x1 + 2 * (c + 320)) = pkh(m0h, m1h);
            } else {
                float b0v = g_obias[c], b1v = g_obias[c + 1];
                if (c < 128) {
                    float ev = g_env[r0];
                    *(float2*)&g_sw[(size_t)r0 * 128 + c] =
                        make_float2((d[0] + b0v) * ev, (d[1] + b1v) * ev);
                } else {
                    float ev = g_env[r1];
                    *(float2*)&g_sw[(size_t)r1 * 128 + (c - 128)] =
                        make_float2((d[2] + b0v) * ev, (d[3] + b1v) * ev);
                }
            }
        }
    }
}

// ---------------- slogdet + combine ----------------
__global__ void __launch_bounds__(32) slogdetK(const float* __restrict__ wfW,
                                               float* __restrict__ out) {
    __shared__ float ldv[32], sgv[32];
    const int b = blockIdx.x, t = threadIdx.x;
    const int spin = t >> 4, d = t & 15;
    float M[8][8];
#pragma unroll
    for (int o = 0; o < 8; ++o)
#pragma unroll
        for (int e = 0; e < 8; ++e)
            M[o][e] = g_sw[(size_t)(b * 16 + spin * 8 + e) * 128 + o * 16 + d];
    float ld = 0.f, sg = 1.f;
    for (int k = 0; k < 8; ++k) {
        int piv = k;
        float mx = fabsf(M[k][k]);
        for (int i2 = k + 1; i2 < 8; ++i2) {
            float v = fabsf(M[i2][k]);
            if (v > mx) { mx = v; piv = i2; }
        }
        if (piv != k) {
            for (int j2 = 0; j2 < 8; ++j2) {
                float tt = M[k][j2]; M[k][j2] = M[piv][j2]; M[piv][j2] = tt;
            }
            sg = -sg;
        }
        float pv = M[k][k];
        ld += logf(fabsf(pv));
        if (pv < 0.f) sg = -sg;
        float inv = 1.0f / pv;
        for (int i2 = k + 1; i2 < 8; ++i2) {
            float f = M[i2][k] * inv;
            for (int j2 = k + 1; j2 < 8; ++j2)
                M[i2][j2] = fmaf(-f, M[k][j2], M[i2][j2]);
        }
    }
    ldv[t] = ld; sgv[t] = sg;
    __syncthreads();
    if (t == 0) {
        float m = -3.402823e38f, ldt[16], sgt[16];
#pragma unroll
        for (int dd = 0; dd < 16; ++dd) {
            ldt[dd] = ldv[dd] + ldv[16 + dd];
            sgt[dd] = sgv[dd] * sgv[16 + dd];
            m = fmaxf(m, ldt[dd]);
        }
        float s = 0.f;
#pragma unroll
        for (int dd = 0; dd < 16; ++dd)
            s += sgt[dd] * expf(ldt[dd] - m) * __ldg(wfW + dd);
        out[b] = logf(fabsf(s)) + m;
    }
}

extern "C" void kernel_launch(void* const* d_in, const int* in_sizes, int n_in,
                              void* d_out, int out_size) {
    const float* r   = (const float*)d_in[0];
    const float* a   = (const float*)d_in[1];
    const float* sW0 = (const float*)d_in[2];
    const float* sb0 = (const float*)d_in[3];
    const float* sW  = (const float*)d_in[4];
    const float* sb  = (const float*)d_in[5];
    const float* pW0 = (const float*)d_in[6];
    const float* pb0 = (const float*)d_in[7];
    const float* pW  = (const float*)d_in[8];
    const float* pb  = (const float*)d_in[9];
    const float* vW  = (const float*)d_in[10];
    const float* vb  = (const float*)d_in[11];
    const float* wuW = (const float*)d_in[12];
    const float* wub = (const float*)d_in[13];
    const float* wdW = (const float*)d_in[14];
    const float* wdb = (const float*)d_in[15];
    const float* wfW = (const float*)d_in[16];
    float* out = (float*)d_out;

    cudaFuncSetAttribute(gemmK<0>, cudaFuncAttributeMaxDynamicSharedMemorySize, GSM);
    cudaFuncSetAttribute(gemmK<1>, cudaFuncAttributeMaxDynamicSharedMemorySize, GSM);
    cudaFuncSetAttribute(gemmK<2>, cudaFuncAttributeMaxDynamicSharedMemorySize, GSM);
    cudaFuncSetAttribute(gemmK<3>, cudaFuncAttributeMaxDynamicSharedMemorySize, GSM);

    prepK<<<256, 256>>>(sW, vW, wuW, wdW, sb, vb, wub, wdb);
    phaseAK<<<BW, 256>>>(r, a, sW0, sb0, pW0, pb0, pW, pb);
    for (int l = 0; l < 5; ++l) {
        pudfillK<<<BW, 512>>>(l);
        gemmK<0><<<dim3(16, 2, 3), 256, GSM>>>(l);
        if (l < 4) {
            gemmK<1><<<dim3(256, 2), 256, GSM>>>(l);
            meansK<<<BW, 256>>>((l & 1) ^ 1);
        } else {
            gemmK<2><<<dim3(256, 2), 256, GSM>>>(l);
        }
    }
    gemmK<3><<<dim3(256, 2), 256, GSM>>>(0);
    slogdetK<<<BW, 32>>>(wfW, out);
}